// round 12
// baseline (speedup 1.0000x reference)
#include <cuda_runtime.h>
#include <math.h>
#include <stdint.h>

#define BB 32
#define CC 256
#define HWD 96
#define ROW4 (HWD/4)         // 24 float4 per row
#define PLANE (HWD*HWD)      // 9216
#define PLANE_BYTES (PLANE*4)
#define NPLANES (BB*CC)      // 8192
#define KK 9
#define W2ROWS (CC*KK)       // 2304
#define CHUNK_B 2            // batches per chunk: 18.9 MB (3 chunks < L2)
#define NCHUNK (BB/CHUNK_B)  // 16
#define CPL (CHUNK_B*CC)     // 512 planes per chunk
#define NT 288               // 24 strips x 12 row-chunks; 36 rows x 8 lanes
#define NDYN (CHUNK_B*64)    // 128 dyn rider blocks per chunk (64/batch)

// scratch (no allocations allowed)
__device__ float g_pooled[NPLANES];
__device__ float g_wdyn[NPLANES * KK];

// ---------------------------------------------------------------------------
struct Row6 { float4 c; float l, r; };

__device__ __forceinline__ Row6 load_row_s(const float* __restrict__ s,
                                           int y, int xb, int x4) {
    Row6 o;
    const float* rp = s + y * HWD;
    o.c = *reinterpret_cast<const float4*>(rp + xb);
    o.l = (x4 == 0)        ? o.c.y : rp[xb - 1];      // reflect col -1 -> 1
    o.r = (x4 == ROW4 - 1) ? o.c.z : rp[xb + 4];      // reflect col 96 -> 94
    return o;
}

__device__ __forceinline__ void row_fma(float4& acc, const Row6& rr,
                                        float wl, float wc, float wr) {
    acc.x += rr.l   * wl + rr.c.x * wc + rr.c.y * wr;
    acc.y += rr.c.x * wl + rr.c.y * wc + rr.c.z * wr;
    acc.z += rr.c.y * wl + rr.c.z * wc + rr.c.w * wr;
    acc.w += rr.c.z * wl + rr.c.w * wc + rr.r   * wr;
}

// ---------------------------------------------------------------------------
// mega kernel: three block types per launch, all deps cross-launch.
//   dyn riders (first NDYN blocks, if dyn_b0>=0): wdyn for chunk pooled last
//     launch. Short critical path (8-way split dots), hidden under the rest.
//   conv blocks (conv_p0>=0): TMA load (L2 hit: pooled 2 launches ago),
//     register-window stencil, __stcs streaming stores.
//   pool blocks (pool_p0>=0): plain cached LDG -> warms L2 for conv in 2
//     launches.
// ---------------------------------------------------------------------------
__global__ __launch_bounds__(NT) void mega_kernel(
    const float* __restrict__ x, float* __restrict__ out,
    const float* __restrict__ w1, const float* __restrict__ b1,
    const float* __restrict__ w2, const float* __restrict__ b2,
    int conv_p0, int pool_p0, int dyn_b0)
{
    const int tid = threadIdx.x;
    __shared__ __align__(16) float s[PLANE];
    __shared__ __align__(8) uint64_t mbar;

    const int n_dyn = (dyn_b0 >= 0) ? NDYN : 0;

    if ((int)blockIdx.x < n_dyn) {
        // ================= dyn rider =======================================
        const int idx  = blockIdx.x;
        const int b    = dyn_b0 + (idx >> 6);       // 64 blocks per batch
        const int rgrp = idx & 63;
        float* ps = s;                               // [0,256)
        float* hs = s + CC;                          // [256,512)

        if (tid < CC) ps[tid] = g_pooled[b * CC + tid];
        __syncthreads();
        if (tid < CC) {
            float acc = b1[tid];
            const float4* __restrict__ wr =
                reinterpret_cast<const float4*>(w1 + (size_t)tid * CC);
            const float4* __restrict__ pv = reinterpret_cast<const float4*>(ps);
#pragma unroll 16
            for (int k = 0; k < CC / 4; ++k) {
                float4 a = pv[k]; float4 w = wr[k];
                acc += a.x * w.x + a.y * w.y + a.z * w.z + a.w * w.w;
            }
            hs[tid] = 0.5f * acc * (1.0f + erff(acc * 0.70710678118654752f));
        }
        __syncthreads();

        const int row = rgrp * 36 + (tid >> 3);     // 64*36 = 2304 rows
        const int l8  = tid & 7;
        const float4* __restrict__ wr =
            reinterpret_cast<const float4*>(w2 + (size_t)row * CC) + l8 * 8;
        const float4* __restrict__ hv =
            reinterpret_cast<const float4*>(hs) + l8 * 8;
        float acc = 0.f;
#pragma unroll
        for (int j = 0; j < 8; ++j) {
            float4 a = hv[j]; float4 w = wr[j];
            acc += a.x * w.x + a.y * w.y + a.z * w.z + a.w * w.w;
        }
#pragma unroll
        for (int o = 4; o > 0; o >>= 1)
            acc += __shfl_xor_sync(0xffffffffu, acc, o);   // within 8-lane group
        if (l8 == 0)
            g_wdyn[(size_t)b * W2ROWS + row] = acc + b2[row];
        return;
    }

    // ---- partition remaining blocks between conv and pool ------------------
    int rem = blockIdx.x - n_dyn;
    int type, idx;
    if (conv_p0 >= 0 && pool_p0 >= 0) { type = rem & 1; idx = rem >> 1; }
    else if (conv_p0 >= 0)            { type = 0;       idx = rem; }
    else                              { type = 1;       idx = rem; }

    if (type == 1) {
        // ================= pool block (cached LDG, warms L2) ===============
        const int plane = pool_p0 + idx;
        const float4* __restrict__ xp =
            reinterpret_cast<const float4*>(x + (size_t)plane * PLANE);
        float sum = 0.f;
#pragma unroll
        for (int it = 0; it < 8; ++it) {            // 2304/288 = 8
            float4 v = xp[tid + it * NT];
            sum += (v.x + v.y) + (v.z + v.w);
        }
#pragma unroll
        for (int o = 16; o > 0; o >>= 1)
            sum += __shfl_xor_sync(0xffffffffu, sum, o);
        const int lane = tid & 31, wid = tid >> 5;
        if (lane == 0) s[wid] = sum;
        __syncthreads();
        if (tid == 0) {
            float t = 0.f;
#pragma unroll
            for (int i = 0; i < 9; ++i) t += s[i];
            g_pooled[plane] = t * (1.0f / (float)PLANE);
        }
        return;
    }

    // ================= conv block (TMA load, reads hit L2) =================
    const int plane = conv_p0 + idx;

    uint32_t s_u32, mbar_u32;
    asm("{ .reg .u64 t; cvta.to.shared.u64 t, %1; cvt.u32.u64 %0, t; }"
        : "=r"(s_u32) : "l"((const void*)s));
    asm("{ .reg .u64 t; cvta.to.shared.u64 t, %1; cvt.u32.u64 %0, t; }"
        : "=r"(mbar_u32) : "l"((const void*)&mbar));

    if (tid == 0) {
        asm volatile("mbarrier.init.shared.b64 [%0], 1;" :: "r"(mbar_u32) : "memory");
        asm volatile("fence.proxy.async.shared::cta;" ::: "memory");
        asm volatile("mbarrier.arrive.expect_tx.shared.b64 _, [%0], %1;"
                     :: "r"(mbar_u32), "r"((unsigned)PLANE_BYTES) : "memory");
        asm volatile(
            "cp.async.bulk.shared::cta.global.mbarrier::complete_tx::bytes "
            "[%0], [%1], %2, [%3];"
            :: "r"(s_u32), "l"(x + (size_t)plane * PLANE),
               "r"((unsigned)PLANE_BYTES), "r"(mbar_u32)
            : "memory");
    }

    float w[KK];
    const float* __restrict__ wd = g_wdyn + (size_t)plane * KK;
#pragma unroll
    for (int i = 0; i < KK; ++i) w[i] = wd[i];

    __syncthreads();
    {
        unsigned done = 0;
        while (!done) {
            asm volatile(
                "{\n .reg .pred p;\n"
                " mbarrier.try_wait.parity.acquire.cta.shared::cta.b64 p, [%1], %2, 0x989680;\n"
                " selp.b32 %0, 1, 0, p;\n}"
                : "=r"(done) : "r"(mbar_u32), "r"(0u) : "memory");
        }
    }

    const int x4 = tid % ROW4;
    const int cy = tid / ROW4;
    const int y0 = cy * 8;
    const int xb = x4 * 4;

    Row6 prev = load_row_s(s, (cy == 0) ? 1 : (y0 - 1), xb, x4);  // reflect -1 -> 1
    Row6 cur  = load_row_s(s, y0, xb, x4);

    float4* __restrict__ o4 =
        reinterpret_cast<float4*>(out + (size_t)plane * PLANE);

#pragma unroll
    for (int i = 0; i < 8; ++i) {
        const int y  = y0 + i;
        const int yn = (y == HWD - 1) ? HWD - 2 : y + 1;          // reflect 96 -> 94
        Row6 nxt = load_row_s(s, yn, xb, x4);
        float4 acc = make_float4(0.f, 0.f, 0.f, 0.f);
        row_fma(acc, prev, w[0], w[1], w[2]);
        row_fma(acc, cur,  w[3], w[4], w[5]);
        row_fma(acc, nxt,  w[6], w[7], w[8]);
        __stcs(&o4[y * ROW4 + x4], acc);                          // evict-first
        prev = cur; cur = nxt;
    }
}

// ---------------------------------------------------------------------------
extern "C" void kernel_launch(void* const* d_in, const int* in_sizes, int n_in,
                              void* d_out, int out_size) {
    const float* x  = (const float*)d_in[0];   // (32,256,96,96)
    const float* w1 = (const float*)d_in[1];   // (256,256)
    const float* b1 = (const float*)d_in[2];   // (256,)
    const float* w2 = (const float*)d_in[3];   // (2304,256)
    const float* b2 = (const float*)d_in[4];   // (2304,)
    float* out = (float*)d_out;

    // L0: pool(0)
    mega_kernel<<<CPL, NT>>>(x, out, w1, b1, w2, b2, -1, 0, -1);
    // L1: pool(1) || dyn(0)
    mega_kernel<<<NDYN + CPL, NT>>>(x, out, w1, b1, w2, b2, -1, CPL, 0);
    // Lk (k=2..15): conv(k-2) || pool(k) || dyn(k-1)
    for (int k = 2; k < NCHUNK; ++k)
        mega_kernel<<<NDYN + 2 * CPL, NT>>>(x, out, w1, b1, w2, b2,
                                            (k - 2) * CPL, k * CPL,
                                            (k - 1) * CHUNK_B);
    // L16: conv(14) || dyn(15)
    mega_kernel<<<NDYN + CPL, NT>>>(x, out, w1, b1, w2, b2,
                                    (NCHUNK - 2) * CPL, -1,
                                    (NCHUNK - 1) * CHUNK_B);
    // L17: conv(15)
    mega_kernel<<<CPL, NT>>>(x, out, w1, b1, w2, b2,
                             (NCHUNK - 1) * CPL, -1, -1);
}

// round 13
// speedup vs baseline: 1.3897x; 1.3897x over previous
#include <cuda_runtime.h>
#include <math.h>
#include <stdint.h>

#define BB 32
#define CC 256
#define HWD 96
#define ROW4 (HWD/4)         // 24 float4 per row
#define PLANE (HWD*HWD)      // 9216
#define PLANE_BYTES (PLANE*4)
#define NPLANES (BB*CC)      // 8192
#define KK 9
#define W2ROWS (CC*KK)       // 2304
#define CHUNK_B 8            // batches per chunk: 75.5 MB (< 126 MB L2)
#define NCHUNK (BB/CHUNK_B)  // 4
#define CPL (CHUNK_B*CC)     // 2048 planes per chunk
#define NT 288
#define NDYN (CHUNK_B*64)    // 512 dyn blocks per chunk

// scratch (no allocations allowed)
__device__ float g_pooled[NPLANES];
__device__ float g_wdyn[NPLANES * KK];

// ---------------------------------------------------------------------------
struct Row6 { float4 c; float l, r; };

__device__ __forceinline__ Row6 load_row_s(const float* __restrict__ s,
                                           int y, int xb, int x4) {
    Row6 o;
    const float* rp = s + y * HWD;
    o.c = *reinterpret_cast<const float4*>(rp + xb);
    o.l = (x4 == 0)        ? o.c.y : rp[xb - 1];      // reflect col -1 -> 1
    o.r = (x4 == ROW4 - 1) ? o.c.z : rp[xb + 4];      // reflect col 96 -> 94
    return o;
}

__device__ __forceinline__ void row_fma(float4& acc, const Row6& rr,
                                        float wl, float wc, float wr) {
    acc.x += rr.l   * wl + rr.c.x * wc + rr.c.y * wr;
    acc.y += rr.c.x * wl + rr.c.y * wc + rr.c.z * wr;
    acc.z += rr.c.y * wl + rr.c.z * wc + rr.c.w * wr;
    acc.w += rr.c.z * wl + rr.c.w * wc + rr.r   * wr;
}

// ---------------------------------------------------------------------------
// mix kernel: even blocks = conv of chunk conv_p0 (REVERSE plane order ->
// reads chase the freshest L2 lines from last launch's pool); odd blocks =
// pool of chunk pool_p0 (cached LDG -> warms L2 for next launch's conv).
// ---------------------------------------------------------------------------
__global__ __launch_bounds__(NT) void mix_kernel(const float* __restrict__ x,
                                                 float* __restrict__ out,
                                                 int conv_p0, int pool_p0) {
    const int tid = threadIdx.x;
    int type, idx;
    if (conv_p0 >= 0 && pool_p0 >= 0) { type = blockIdx.x & 1; idx = blockIdx.x >> 1; }
    else if (conv_p0 >= 0)            { type = 0;              idx = blockIdx.x; }
    else                              { type = 1;              idx = blockIdx.x; }

    __shared__ __align__(16) float s[PLANE];
    __shared__ __align__(8) uint64_t mbar;

    if (type == 1) {
        // ---------------- pool block (cached LDG, warms L2) -----------------
        const int plane = pool_p0 + idx;
        const float4* __restrict__ xp =
            reinterpret_cast<const float4*>(x + (size_t)plane * PLANE);
        float sum = 0.f;
#pragma unroll
        for (int it = 0; it < 8; ++it) {            // 2304/288 = 8
            float4 v = xp[tid + it * NT];
            sum += (v.x + v.y) + (v.z + v.w);
        }
#pragma unroll
        for (int o = 16; o > 0; o >>= 1)
            sum += __shfl_xor_sync(0xffffffffu, sum, o);
        const int lane = tid & 31, wid = tid >> 5;
        if (lane == 0) s[wid] = sum;
        __syncthreads();
        if (tid == 0) {
            float t = 0.f;
#pragma unroll
            for (int i = 0; i < 9; ++i) t += s[i];
            g_pooled[plane] = t * (1.0f / (float)PLANE);
        }
        return;
    }

    // ---------------- conv block (TMA load; reverse order for L2 hits) ------
    const int plane = conv_p0 + (CPL - 1 - idx);

    uint32_t s_u32, mbar_u32;
    asm("{ .reg .u64 t; cvta.to.shared.u64 t, %1; cvt.u32.u64 %0, t; }"
        : "=r"(s_u32) : "l"((const void*)s));
    asm("{ .reg .u64 t; cvta.to.shared.u64 t, %1; cvt.u32.u64 %0, t; }"
        : "=r"(mbar_u32) : "l"((const void*)&mbar));

    if (tid == 0) {
        asm volatile("mbarrier.init.shared.b64 [%0], 1;" :: "r"(mbar_u32) : "memory");
        asm volatile("fence.proxy.async.shared::cta;" ::: "memory");
        asm volatile("mbarrier.arrive.expect_tx.shared.b64 _, [%0], %1;"
                     :: "r"(mbar_u32), "r"((unsigned)PLANE_BYTES) : "memory");
        asm volatile(
            "cp.async.bulk.shared::cta.global.mbarrier::complete_tx::bytes "
            "[%0], [%1], %2, [%3];"
            :: "r"(s_u32), "l"(x + (size_t)plane * PLANE),
               "r"((unsigned)PLANE_BYTES), "r"(mbar_u32)
            : "memory");
    }

    float w[KK];
    const float* __restrict__ wd = g_wdyn + (size_t)plane * KK;
#pragma unroll
    for (int i = 0; i < KK; ++i) w[i] = wd[i];

    __syncthreads();
    {
        unsigned done = 0;
        while (!done) {
            asm volatile(
                "{\n .reg .pred p;\n"
                " mbarrier.try_wait.parity.acquire.cta.shared::cta.b64 p, [%1], %2, 0x989680;\n"
                " selp.b32 %0, 1, 0, p;\n}"
                : "=r"(done) : "r"(mbar_u32), "r"(0u) : "memory");
        }
    }

    const int x4 = tid % ROW4;
    const int cy = tid / ROW4;
    const int y0 = cy * 8;
    const int xb = x4 * 4;

    Row6 prev = load_row_s(s, (cy == 0) ? 1 : (y0 - 1), xb, x4);  // reflect -1 -> 1
    Row6 cur  = load_row_s(s, y0, xb, x4);

    float4* __restrict__ o4 =
        reinterpret_cast<float4*>(out + (size_t)plane * PLANE);

#pragma unroll
    for (int i = 0; i < 8; ++i) {
        const int y  = y0 + i;
        const int yn = (y == HWD - 1) ? HWD - 2 : y + 1;          // reflect 96 -> 94
        Row6 nxt = load_row_s(s, yn, xb, x4);
        float4 acc = make_float4(0.f, 0.f, 0.f, 0.f);
        row_fma(acc, prev, w[0], w[1], w[2]);
        row_fma(acc, cur,  w[3], w[4], w[5]);
        row_fma(acc, nxt,  w[6], w[7], w[8]);
        __stcs(&o4[y * ROW4 + x4], acc);                          // evict-first
        prev = cur; cur = nxt;
    }
}

// ---------------------------------------------------------------------------
// dyn kernel, wide/short-latency. grid = 64*CHUNK_B blocks of 288 threads.
// Block (b, rgrp): recompute h (w1 L2-hot), then 36 rows of w2 with 8-lane
// split dots + shfl reduce. Wall time ~3 us.
// ---------------------------------------------------------------------------
__global__ __launch_bounds__(NT) void dyn_kernel(const float* __restrict__ w1,
                                                 const float* __restrict__ b1,
                                                 const float* __restrict__ w2,
                                                 const float* __restrict__ b2,
                                                 int b0) {
    const int bid  = blockIdx.x;
    const int b    = b0 + (bid >> 6);
    const int rgrp = bid & 63;
    const int tid  = threadIdx.x;
    __shared__ float ps[CC];
    __shared__ float hs[CC];

    if (tid < CC) ps[tid] = g_pooled[b * CC + tid];
    __syncthreads();
    if (tid < CC) {
        float acc = b1[tid];
        const float4* __restrict__ wr =
            reinterpret_cast<const float4*>(w1 + (size_t)tid * CC);
        const float4* __restrict__ pv = reinterpret_cast<const float4*>(ps);
#pragma unroll 16
        for (int k = 0; k < CC / 4; ++k) {
            float4 a = pv[k]; float4 w = wr[k];
            acc += a.x * w.x + a.y * w.y + a.z * w.z + a.w * w.w;
        }
        hs[tid] = 0.5f * acc * (1.0f + erff(acc * 0.70710678118654752f));
    }
    __syncthreads();

    const int row = rgrp * 36 + (tid >> 3);        // 64*36 = 2304 rows
    const int l8  = tid & 7;
    const float4* __restrict__ wr =
        reinterpret_cast<const float4*>(w2 + (size_t)row * CC) + l8 * 8;
    const float4* __restrict__ hv =
        reinterpret_cast<const float4*>(hs) + l8 * 8;
    float acc = 0.f;
#pragma unroll
    for (int j = 0; j < 8; ++j) {
        float4 a = hv[j]; float4 w = wr[j];
        acc += a.x * w.x + a.y * w.y + a.z * w.z + a.w * w.w;
    }
#pragma unroll
    for (int o = 4; o > 0; o >>= 1)
        acc += __shfl_xor_sync(0xffffffffu, acc, o);   // within 8-lane group
    if (l8 == 0)
        g_wdyn[(size_t)b * W2ROWS + row] = acc + b2[row];
}

// ---------------------------------------------------------------------------
extern "C" void kernel_launch(void* const* d_in, const int* in_sizes, int n_in,
                              void* d_out, int out_size) {
    const float* x  = (const float*)d_in[0];   // (32,256,96,96)
    const float* w1 = (const float*)d_in[1];   // (256,256)
    const float* b1 = (const float*)d_in[2];   // (256,)
    const float* w2 = (const float*)d_in[3];   // (2304,256)
    const float* b2 = (const float*)d_in[4];   // (2304,)
    float* out = (float*)d_out;

    // L0: pool(C0)
    mix_kernel<<<CPL, NT>>>(x, out, -1, 0);
    dyn_kernel<<<NDYN, NT>>>(w1, b1, w2, b2, 0);
    // steady: conv(c) || pool(c+1), then dyn(c+1)
    for (int c = 0; c < NCHUNK - 1; ++c) {
        mix_kernel<<<2 * CPL, NT>>>(x, out, c * CPL, (c + 1) * CPL);
        dyn_kernel<<<NDYN, NT>>>(w1, b1, w2, b2, (c + 1) * CHUNK_B);
    }
    // tail: conv(C3)
    mix_kernel<<<CPL, NT>>>(x, out, (NCHUNK - 1) * CPL, -1);
}

// round 14
// speedup vs baseline: 1.8034x; 1.2977x over previous
#include <cuda_runtime.h>
#include <math.h>
#include <stdint.h>

#define BB 32
#define CC 256
#define HWD 96
#define ROW4 (HWD/4)         // 24 float4 per row
#define PLANE (HWD*HWD)      // 9216
#define PLANE_BYTES (PLANE*4)
#define NPLANES (BB*CC)      // 8192
#define KK 9
#define W2ROWS (CC*KK)       // 2304
#define CHUNK_B 4            // batches per chunk (37.7 MB; <=3 live in L2)
#define NCHUNK (BB/CHUNK_B)  // 8
#define CPL (CHUNK_B*CC)     // 1024 planes per chunk
#define NT 288

// scratch (no allocations allowed)
__device__ float g_pooled[NPLANES];
__device__ float g_h[BB*CC];
__device__ float g_wdyn[NPLANES * KK];

// ---------------------------------------------------------------------------
// pool: 1 block = 1 plane (256 thr). Cached LDG warms L2 for conv.
// ---------------------------------------------------------------------------
__global__ __launch_bounds__(256) void pool_kernel(const float* __restrict__ x,
                                                   int p0) {
    const int plane = p0 + blockIdx.x;
    const float4* __restrict__ xp =
        reinterpret_cast<const float4*>(x + (size_t)plane * PLANE);
    float sum = 0.f;
#pragma unroll
    for (int it = 0; it < 9; ++it) {
        float4 v = xp[threadIdx.x + it * 256];
        sum += (v.x + v.y) + (v.z + v.w);
    }
#pragma unroll
    for (int o = 16; o > 0; o >>= 1)
        sum += __shfl_xor_sync(0xffffffffu, sum, o);
    __shared__ float ws[8];
    const int lane = threadIdx.x & 31, wid = threadIdx.x >> 5;
    if (lane == 0) ws[wid] = sum;
    __syncthreads();
    if (threadIdx.x == 0) {
        float t = 0.f;
#pragma unroll
        for (int i = 0; i < 8; ++i) t += ws[i];
        g_pooled[plane] = t * (1.0f / (float)PLANE);
    }
}

// ---------------------------------------------------------------------------
// dyn1: h = gelu(pooled @ w1^T + b1). 1 block per batch (4 blocks/chunk).
// ---------------------------------------------------------------------------
__global__ __launch_bounds__(256) void dyn1_kernel(const float* __restrict__ w1,
                                                   const float* __restrict__ b1,
                                                   int b0) {
    const int b = b0 + blockIdx.x;
    const int c = threadIdx.x;
    __shared__ float ps[CC];
    ps[c] = g_pooled[b * CC + c];
    __syncthreads();
    float acc = b1[c];
    const float4* __restrict__ wr =
        reinterpret_cast<const float4*>(w1 + (size_t)c * CC);
    const float4* __restrict__ pv = reinterpret_cast<const float4*>(ps);
#pragma unroll 16
    for (int k = 0; k < CC / 4; ++k) {
        float4 a = pv[k]; float4 w = wr[k];
        acc += a.x * w.x + a.y * w.y + a.z * w.z + a.w * w.w;
    }
    g_h[b * CC + c] = 0.5f * acc * (1.0f + erff(acc * 0.70710678118654752f));
}

// ---------------------------------------------------------------------------
// dyn2: wdyn = h @ w2^T + b2. 64 blocks/batch, 36 rows/block, 8-lane split
// dots + shfl. Reads precomputed h (1 KB) — no w1 replay.
// ---------------------------------------------------------------------------
__global__ __launch_bounds__(NT) void dyn2_kernel(const float* __restrict__ w2,
                                                  const float* __restrict__ b2,
                                                  int b0) {
    const int b    = b0 + (blockIdx.x >> 6);
    const int rgrp = blockIdx.x & 63;
    const int tid  = threadIdx.x;
    __shared__ float hs[CC];
    if (tid < CC) hs[tid] = g_h[b * CC + tid];
    __syncthreads();

    const int row = rgrp * 36 + (tid >> 3);        // 64*36 = 2304 rows
    const int l8  = tid & 7;
    const float4* __restrict__ wr =
        reinterpret_cast<const float4*>(w2 + (size_t)row * CC) + l8 * 8;
    const float4* __restrict__ hv =
        reinterpret_cast<const float4*>(hs) + l8 * 8;
    float acc = 0.f;
#pragma unroll
    for (int j = 0; j < 8; ++j) {
        float4 a = hv[j]; float4 w = wr[j];
        acc += a.x * w.x + a.y * w.y + a.z * w.z + a.w * w.w;
    }
#pragma unroll
    for (int o = 4; o > 0; o >>= 1)
        acc += __shfl_xor_sync(0xffffffffu, acc, o);
    if (l8 == 0)
        g_wdyn[(size_t)b * W2ROWS + row] = acc + b2[row];
}

// ---------------------------------------------------------------------------
// conv: TMA bulk load plane -> smem (L2-hit: pool just touched it), register
// sliding window, streaming STG.128.
// ---------------------------------------------------------------------------
struct Row6 { float4 c; float l, r; };

__device__ __forceinline__ Row6 load_row_s(const float* __restrict__ s,
                                           int y, int xb, int x4) {
    Row6 o;
    const float* rp = s + y * HWD;
    o.c = *reinterpret_cast<const float4*>(rp + xb);
    o.l = (x4 == 0)        ? o.c.y : rp[xb - 1];      // reflect col -1 -> 1
    o.r = (x4 == ROW4 - 1) ? o.c.z : rp[xb + 4];      // reflect col 96 -> 94
    return o;
}

__device__ __forceinline__ void row_fma(float4& acc, const Row6& rr,
                                        float wl, float wc, float wr) {
    acc.x += rr.l   * wl + rr.c.x * wc + rr.c.y * wr;
    acc.y += rr.c.x * wl + rr.c.y * wc + rr.c.z * wr;
    acc.z += rr.c.y * wl + rr.c.z * wc + rr.c.w * wr;
    acc.w += rr.c.z * wl + rr.c.w * wc + rr.r   * wr;
}

__global__ __launch_bounds__(NT) void conv_kernel(const float* __restrict__ x,
                                                  float* __restrict__ out,
                                                  int p0) {
    const int plane = p0 + blockIdx.x;
    __shared__ __align__(16) float s[PLANE];
    __shared__ __align__(8) uint64_t mbar;
    const int tid = threadIdx.x;

    uint32_t s_u32, mbar_u32;
    asm("{ .reg .u64 t; cvta.to.shared.u64 t, %1; cvt.u32.u64 %0, t; }"
        : "=r"(s_u32) : "l"((const void*)s));
    asm("{ .reg .u64 t; cvta.to.shared.u64 t, %1; cvt.u32.u64 %0, t; }"
        : "=r"(mbar_u32) : "l"((const void*)&mbar));

    if (tid == 0) {
        asm volatile("mbarrier.init.shared.b64 [%0], 1;" :: "r"(mbar_u32) : "memory");
        asm volatile("fence.proxy.async.shared::cta;" ::: "memory");
        asm volatile("mbarrier.arrive.expect_tx.shared.b64 _, [%0], %1;"
                     :: "r"(mbar_u32), "r"((unsigned)PLANE_BYTES) : "memory");
        asm volatile(
            "cp.async.bulk.shared::cta.global.mbarrier::complete_tx::bytes "
            "[%0], [%1], %2, [%3];"
            :: "r"(s_u32), "l"(x + (size_t)plane * PLANE),
               "r"((unsigned)PLANE_BYTES), "r"(mbar_u32)
            : "memory");
    }

    float w[KK];
    const float* __restrict__ wd = g_wdyn + (size_t)plane * KK;
#pragma unroll
    for (int i = 0; i < KK; ++i) w[i] = wd[i];

    __syncthreads();
    {
        unsigned done = 0;
        while (!done) {
            asm volatile(
                "{\n .reg .pred p;\n"
                " mbarrier.try_wait.parity.acquire.cta.shared::cta.b64 p, [%1], %2, 0x989680;\n"
                " selp.b32 %0, 1, 0, p;\n}"
                : "=r"(done) : "r"(mbar_u32), "r"(0u) : "memory");
        }
    }

    const int x4 = tid % ROW4;
    const int cy = tid / ROW4;
    const int y0 = cy * 8;
    const int xb = x4 * 4;

    Row6 prev = load_row_s(s, (cy == 0) ? 1 : (y0 - 1), xb, x4);  // reflect -1 -> 1
    Row6 cur  = load_row_s(s, y0, xb, x4);

    float4* __restrict__ o4 =
        reinterpret_cast<float4*>(out + (size_t)plane * PLANE);

#pragma unroll
    for (int i = 0; i < 8; ++i) {
        const int y  = y0 + i;
        const int yn = (y == HWD - 1) ? HWD - 2 : y + 1;          // reflect 96 -> 94
        Row6 nxt = load_row_s(s, yn, xb, x4);
        float4 acc = make_float4(0.f, 0.f, 0.f, 0.f);
        row_fma(acc, prev, w[0], w[1], w[2]);
        row_fma(acc, cur,  w[3], w[4], w[5]);
        row_fma(acc, nxt,  w[6], w[7], w[8]);
        __stcs(&o4[y * ROW4 + x4], acc);                          // evict-first
        prev = cur; cur = nxt;
    }
}

// ---------------------------------------------------------------------------
// Stream/event topology, created once at load (host objects, no device mem).
// ---------------------------------------------------------------------------
static cudaStream_t sB, sC;
static cudaEvent_t  ePool[NCHUNK], eDyn[NCHUNK], eTail;
static struct GraphInit {
    GraphInit() {
        cudaStreamCreateWithFlags(&sB, cudaStreamNonBlocking);
        cudaStreamCreateWithFlags(&sC, cudaStreamNonBlocking);
        for (int i = 0; i < NCHUNK; ++i) {
            cudaEventCreateWithFlags(&ePool[i], cudaEventDisableTiming);
            cudaEventCreateWithFlags(&eDyn[i],  cudaEventDisableTiming);
        }
        cudaEventCreate(&eTail, cudaEventDisableTiming);
    }
} g_init;

extern "C" void kernel_launch(void* const* d_in, const int* in_sizes, int n_in,
                              void* d_out, int out_size) {
    const float* x  = (const float*)d_in[0];   // (32,256,96,96)
    const float* w1 = (const float*)d_in[1];   // (256,256)
    const float* b1 = (const float*)d_in[2];   // (256,)
    const float* w2 = (const float*)d_in[3];   // (2304,256)
    const float* b2 = (const float*)d_in[4];   // (2304,)
    float* out = (float*)d_out;

    // s0 (capture stream): pools, chunk by chunk; event after each.
    for (int c = 0; c < NCHUNK; ++c) {
        pool_kernel<<<CPL, 256>>>(x, c * CPL);
        cudaEventRecord(ePool[c], 0);
    }
    // sC: dyn chain per chunk, gated on that chunk's pool.
    for (int c = 0; c < NCHUNK; ++c) {
        cudaStreamWaitEvent(sC, ePool[c], 0);
        dyn1_kernel<<<CHUNK_B, 256, 0, sC>>>(w1, b1, c * CHUNK_B);
        dyn2_kernel<<<CHUNK_B * 64, NT, 0, sC>>>(w2, b2, c * CHUNK_B);
        cudaEventRecord(eDyn[c], sC);
    }
    // sB: conv per chunk, gated on that chunk's dyn. Runs concurrent with
    // later pools on s0 (chunk c is L2-resident from pool_kernel(c)).
    for (int c = 0; c < NCHUNK; ++c) {
        cudaStreamWaitEvent(sB, eDyn[c], 0);
        conv_kernel<<<CPL, NT, 0, sB>>>(x, out, c * CPL);
    }
    cudaEventRecord(eTail, sB);
    // join everything back onto the capture stream
    cudaStreamWaitEvent(0, eTail, 0);
}